// round 9
// baseline (speedup 1.0000x reference)
#include <cuda_runtime.h>
#include <cstddef>

// Mip chain: [6, 2048, 2048, 3] f32 -> repeated 2x2 avg pool down to 16.
// Output = concat(base, mip1..mip7).

#define R0 2048
#define OFF1 75497472ull
#define OFF2 94371840ull
#define OFF3 99090432ull
#define OFF4 100270080ull
#define OFF5 100564992ull
#define OFF6 100638720ull
#define OFF7 100657152ull

// ---------------- Kernel A: 64x64 tiles -> L0 copy + mip1 + mip2 + mip3 ----
// smem (floats): slab sums 16x192=3072 | m1 16x96=1536 | m2 16x48=768
#define S_SLAB 0
#define S_M1   3072
#define S_M2   4608
#define A_SMEM 5376

__global__ __launch_bounds__(256) void mip_stageA(const float* __restrict__ base,
                                                  float* __restrict__ out) {
    __shared__ float sm[A_SMEM];
    const int f  = blockIdx.z;
    const int tX = blockIdx.x;   // 0..31
    const int tY = blockIdx.y;   // 0..31
    const int t  = threadIdx.x;  // 0..255

    // 768 units per 32-row slab: unit = (row-pair 0..15) * 48 + f4col
    int aa[3], cc[3];
    #pragma unroll
    for (int k = 0; k < 3; k++) {
        const int unit = k * 256 + t;
        aa[k] = unit / 48;
        cc[k] = unit - aa[k] * 48;
    }

    const size_t tile = ((size_t)(f * R0 + tY * 64) * R0 + tX * 64) * 3;

    // preload slab 0 (raw rows held in regs until L0 store)
    float4 va[3], vb[3];
    #pragma unroll
    for (int k = 0; k < 3; k++) {
        const size_t g0 = tile + (size_t)(2 * aa[k]) * (R0 * 3);
        va[k] = reinterpret_cast<const float4*>(base + g0)[cc[k]];
        vb[k] = reinterpret_cast<const float4*>(base + g0 + (size_t)(R0 * 3))[cc[k]];
    }

    #pragma unroll
    for (int s = 0; s < 2; s++) {
        // ---- L0 copy + publish vertical sums ----
        #pragma unroll
        for (int k = 0; k < 3; k++) {
            const size_t g0 = tile + (size_t)(s * 32 + 2 * aa[k]) * (R0 * 3);
            reinterpret_cast<float4*>(out + g0)[cc[k]] = va[k];
            reinterpret_cast<float4*>(out + g0 + (size_t)(R0 * 3))[cc[k]] = vb[k];
            float4 sv;
            sv.x = va[k].x + vb[k].x; sv.y = va[k].y + vb[k].y;
            sv.z = va[k].z + vb[k].z; sv.w = va[k].w + vb[k].w;
            reinterpret_cast<float4*>(sm + S_SLAB)[aa[k] * 48 + cc[k]] = sv;
        }
        __syncthreads();

        // ---- prefetch slab 1 while mip1/mip2 run ----
        if (s == 0) {
            #pragma unroll
            for (int k = 0; k < 3; k++) {
                const size_t g0 = tile + (size_t)(32 + 2 * aa[k]) * (R0 * 3);
                va[k] = reinterpret_cast<const float4*>(base + g0)[cc[k]];
                vb[k] = reinterpret_cast<const float4*>(base + g0 + (size_t)(R0 * 3))[cc[k]];
            }
        }

        // ---- mip1: 16 rows x 32 px, 2 px per thread ----
        {
            const int r1 = t >> 4;            // 0..15
            const int c1 = (t & 15) * 2;      // even
            const float* in = sm + S_SLAB + r1 * 192 + c1 * 6;  // vertical sums
            const float v0 = (in[0] + in[3]) * 0.25f;
            const float v1 = (in[1] + in[4]) * 0.25f;
            const float v2 = (in[2] + in[5]) * 0.25f;
            const float v3 = (in[6] + in[9]) * 0.25f;
            const float v4 = (in[7] + in[10]) * 0.25f;
            const float v5 = (in[8] + in[11]) * 0.25f;
            const int y1 = tY * 32 + s * 16 + r1;
            const int x1 = tX * 32 + c1;
            float2* o = reinterpret_cast<float2*>(out + OFF1 +
                          ((size_t)(f * 1024 + y1) * 1024 + x1) * 3);
            o[0] = make_float2(v0, v1);
            o[1] = make_float2(v2, v3);
            o[2] = make_float2(v4, v5);
            float* m1 = sm + S_M1 + r1 * 96 + c1 * 3;
            m1[0] = v0; m1[1] = v1; m1[2] = v2;
            m1[3] = v3; m1[4] = v4; m1[5] = v5;
        }
        __syncthreads();

        // ---- mip2: 8 rows x 16 px (threads 0..127) ----
        if (t < 128) {
            const int r2 = t >> 4;            // 0..7
            const int c2 = t & 15;
            const float* ra = sm + S_M1 + (2 * r2) * 96 + c2 * 6;
            const float* rb = ra + 96;
            const float vr = (ra[0] + ra[3] + rb[0] + rb[3]) * 0.25f;
            const float vg = (ra[1] + ra[4] + rb[1] + rb[4]) * 0.25f;
            const float vb2 = (ra[2] + ra[5] + rb[2] + rb[5]) * 0.25f;
            const int y2 = tY * 16 + s * 8 + r2;
            const int x2 = tX * 16 + c2;
            float* o = out + OFF2 + ((size_t)(f * 512 + y2) * 512 + x2) * 3;
            o[0] = vr; o[1] = vg; o[2] = vb2;
            float* m2 = sm + S_M2 + (s * 8 + r2) * 48 + c2 * 3;
            m2[0] = vr; m2[1] = vg; m2[2] = vb2;
        }
        __syncthreads();    // slab buf + m1 free for next iteration
    }

    // ---- mip3: 8x8 (threads 0..63), global only ----
    if (t < 64) {
        const int r = t >> 3, c = t & 7;
        const float* ra = sm + S_M2 + (2 * r) * 48 + c * 6;
        const float* rb = ra + 48;
        const float vr = (ra[0] + ra[3] + rb[0] + rb[3]) * 0.25f;
        const float vg = (ra[1] + ra[4] + rb[1] + rb[4]) * 0.25f;
        const float vb2 = (ra[2] + ra[5] + rb[2] + rb[5]) * 0.25f;
        float* o = out + OFF3 + ((size_t)(f * 256 + tY * 8 + r) * 256 + tX * 8 + c) * 3;
        o[0] = vr; o[1] = vg; o[2] = vb2;
    }
}

// ---------------- Kernel B: mip3 -> mip4..mip7; 24 independent blocks -------
// block = one quadrant (128x128 of mip3) of one face.
#define B_M5 0          // 32x32x3 = 3072
#define B_M6 3072       // 16x16x3 = 768
#define B_SMEM 3840

__global__ __launch_bounds__(256) void mip_stageB(float* __restrict__ out) {
    __shared__ float sm[B_SMEM];
    const int f  = blockIdx.x >> 2;
    const int q  = blockIdx.x & 3;
    const int qy = q >> 1, qx = q & 1;
    const int t  = threadIdx.x;

    const float* m3 = out + OFF3 + (size_t)f * (256 * 256 * 3);
    float* m4 = out + OFF4 + (size_t)f * (128 * 128 * 3);
    float* m5g = out + OFF5 + (size_t)f * (64 * 64 * 3);
    float* m6g = out + OFF6 + (size_t)f * (32 * 32 * 3);
    float* m7g = out + OFF7 + (size_t)f * (16 * 16 * 3);

    // each thread: 4 mip5 px; per px compute 4 mip4 px from 16 mip3 px
    #pragma unroll
    for (int i = 0; i < 4; i++) {
        const int p = i * 256 + t;          // 0..1023 within 32x32 quadrant
        const int y5 = qy * 32 + (p >> 5);
        const int x5 = qx * 32 + (p & 31);
        float s5r = 0.f, s5g = 0.f, s5b = 0.f;
        #pragma unroll
        for (int dy = 0; dy < 2; dy++)
            #pragma unroll
            for (int dx = 0; dx < 2; dx++) {
                const int y4 = 2 * y5 + dy, x4 = 2 * x5 + dx;
                float r = 0.f, g = 0.f, b = 0.f;
                #pragma unroll
                for (int ey = 0; ey < 2; ey++) {
                    const float* row = m3 + ((2 * y4 + ey) * 256 + 2 * x4) * 3;
                    r += row[0] + row[3];
                    g += row[1] + row[4];
                    b += row[2] + row[5];
                }
                r *= 0.25f; g *= 0.25f; b *= 0.25f;
                float* o4 = m4 + (y4 * 128 + x4) * 3;
                o4[0] = r; o4[1] = g; o4[2] = b;
                s5r += r; s5g += g; s5b += b;
            }
        s5r *= 0.25f; s5g *= 0.25f; s5b *= 0.25f;
        float* o5 = m5g + (y5 * 64 + x5) * 3;
        o5[0] = s5r; o5[1] = s5g; o5[2] = s5b;
        float* l5 = sm + B_M5 + p * 3;
        l5[0] = s5r; l5[1] = s5g; l5[2] = s5b;
    }
    __syncthreads();

    // mip6: 16x16 quadrant, 1 px per thread
    {
        const int yq = t >> 4, xq = t & 15;
        const float* ra = sm + B_M5 + ((2 * yq) * 32 + 2 * xq) * 3;
        const float* rb = ra + 32 * 3;
        const float vr = (ra[0] + ra[3] + rb[0] + rb[3]) * 0.25f;
        const float vg = (ra[1] + ra[4] + rb[1] + rb[4]) * 0.25f;
        const float vb = (ra[2] + ra[5] + rb[2] + rb[5]) * 0.25f;
        float* o = m6g + ((qy * 16 + yq) * 32 + qx * 16 + xq) * 3;
        o[0] = vr; o[1] = vg; o[2] = vb;
        float* l6 = sm + B_M6 + (yq * 16 + xq) * 3;
        l6[0] = vr; l6[1] = vg; l6[2] = vb;
    }
    __syncthreads();

    // mip7: 8x8 quadrant (threads 0..63)
    if (t < 64) {
        const int yq = t >> 3, xq = t & 7;
        const float* ra = sm + B_M6 + ((2 * yq) * 16 + 2 * xq) * 3;
        const float* rb = ra + 16 * 3;
        const float vr = (ra[0] + ra[3] + rb[0] + rb[3]) * 0.25f;
        const float vg = (ra[1] + ra[4] + rb[1] + rb[4]) * 0.25f;
        const float vb = (ra[2] + ra[5] + rb[2] + rb[5]) * 0.25f;
        float* o = m7g + ((qy * 8 + yq) * 16 + qx * 8 + xq) * 3;
        o[0] = vr; o[1] = vg; o[2] = vb;
    }
}

extern "C" void kernel_launch(void* const* d_in, const int* in_sizes, int n_in,
                              void* d_out, int out_size) {
    const float* base = (const float*)d_in[0];
    float* out = (float*)d_out;
    dim3 gA(32, 32, 6);
    mip_stageA<<<gA, 256>>>(base, out);
    mip_stageB<<<24, 256>>>(out);
}

// round 10
// speedup vs baseline: 1.0328x; 1.0328x over previous
#include <cuda_runtime.h>
#include <cstddef>

// Mip chain: [6, 2048, 2048, 3] f32 -> repeated 2x2 avg pool down to 16.
// Output = concat(base, mip1..mip7).

#define R0 2048
#define OFF1 75497472ull
#define OFF2 94371840ull
#define OFF3 99090432ull
#define OFF4 100270080ull
#define OFF5 100564992ull
#define OFF6 100638720ull
#define OFF7 100657152ull

// smem layout (floats)
#define S_B0   0        // sum slab buf A: 8 rows x 384 = 3072
#define S_B1   3072     // sum slab buf B: 3072
#define S_M2   6144     // mip2 tile: 32 x 96 = 3072
#define S_M3   0        // tail reuses buf region
#define S_M4   1024
#define S_M5   2048
#define S_M6   2560
#define SMEM_FLOATS 9216

// One block = 128x128 tile -> its piece of every level incl. one mip7 px.
// Slab = 16 raw rows. Double-buffered vertical sums -> ONE barrier per slab.
// A lane owns a 2x2 mip1 quad -> computes its mip2 pixel in registers
// (no mip1 smem staging, no second barrier).
__global__ __launch_bounds__(256) void mip_all(const float* __restrict__ base,
                                               float* __restrict__ out) {
    __shared__ float sm[SMEM_FLOATS];
    const int f  = blockIdx.z;
    const int tX = blockIdx.x;   // 0..15
    const int tY = blockIdx.y;   // 0..15
    const int t  = threadIdx.x;  // 0..255
    const int w  = t >> 5;       // warp 0..7
    const int l  = t & 31;       // lane

    // load units: 8 row-pairs x 96 f4 cols = 768, 3 per thread
    int aa[3], cc[3];
    #pragma unroll
    for (int k = 0; k < 3; k++) {
        const int unit = k * 256 + t;
        aa[k] = unit / 96;
        cc[k] = unit - aa[k] * 96;
    }

    const size_t tile = ((size_t)(f * R0 + tY * 128) * R0 + tX * 128) * 3;

    // prologue: slab 0 load + L0 copy + vertical reduce (keep only sums)
    float4 sv[3];
    #pragma unroll
    for (int k = 0; k < 3; k++) {
        const size_t g0 = tile + (size_t)(2 * aa[k]) * (R0 * 3);
        const float4 va = reinterpret_cast<const float4*>(base + g0)[cc[k]];
        const float4 vb = reinterpret_cast<const float4*>(base + g0 + (size_t)(R0 * 3))[cc[k]];
        reinterpret_cast<float4*>(out + g0)[cc[k]] = va;
        reinterpret_cast<float4*>(out + g0 + (size_t)(R0 * 3))[cc[k]] = vb;
        sv[k].x = va.x + vb.x; sv[k].y = va.y + vb.y;
        sv[k].z = va.z + vb.z; sv[k].w = va.w + vb.w;
    }

    for (int s = 0; s < 8; s++) {
        // ---- publish this slab's vertical sums into buf[s&1] ----
        float* buf = sm + (s & 1) * 3072;
        #pragma unroll
        for (int k = 0; k < 3; k++)
            reinterpret_cast<float4*>(buf)[aa[k] * 96 + cc[k]] = sv[k];
        __syncthreads();   // the ONLY barrier per slab

        // ---- prefetch slab s+1: load + L0 copy + reduce ----
        if (s < 7) {
            const int y0 = (s + 1) * 16;
            #pragma unroll
            for (int k = 0; k < 3; k++) {
                const size_t g0 = tile + (size_t)(y0 + 2 * aa[k]) * (R0 * 3);
                const float4 va = reinterpret_cast<const float4*>(base + g0)[cc[k]];
                const float4 vb = reinterpret_cast<const float4*>(base + g0 + (size_t)(R0 * 3))[cc[k]];
                reinterpret_cast<float4*>(out + g0)[cc[k]] = va;
                reinterpret_cast<float4*>(out + g0 + (size_t)(R0 * 3))[cc[k]] = vb;
                sv[k].x = va.x + vb.x; sv[k].y = va.y + vb.y;
                sv[k].z = va.z + vb.z; sv[k].w = va.w + vb.w;
            }
        }

        // ---- mip1 + mip2 (warps 0..3): lane owns 2x2 mip1 quad ----
        if (w < 4) {
            // sum rows 2w, 2w+1; 12 floats each starting at float offset 12*l
            const float4* ra = reinterpret_cast<const float4*>(buf + (2 * w) * 384 + 12 * l);
            const float4* rb = reinterpret_cast<const float4*>(buf + (2 * w + 1) * 384 + 12 * l);
            const float4 a0 = ra[0], a1 = ra[1], a2 = ra[2];
            const float4 b0 = rb[0], b1 = rb[1], b2 = rb[2];

            // mip1 px (2w, 2l): channels from floats 0..5 of row a
            const float p00r = (a0.x + a0.w) * 0.25f;
            const float p00g = (a0.y + a1.x) * 0.25f;
            const float p00b = (a0.z + a1.y) * 0.25f;
            // mip1 px (2w, 2l+1): floats 6..11 of row a
            const float p01r = (a1.z + a2.y) * 0.25f;
            const float p01g = (a1.w + a2.z) * 0.25f;
            const float p01b = (a2.x + a2.w) * 0.25f;
            // mip1 px (2w+1, 2l) / (2w+1, 2l+1) from row b
            const float p10r = (b0.x + b0.w) * 0.25f;
            const float p10g = (b0.y + b1.x) * 0.25f;
            const float p10b = (b0.z + b1.y) * 0.25f;
            const float p11r = (b1.z + b2.y) * 0.25f;
            const float p11g = (b1.w + b2.z) * 0.25f;
            const float p11b = (b2.x + b2.w) * 0.25f;

            // write mip1: 2 rows x 2 px (3 float2 per row, lane-contiguous 24B)
            const int y1 = tY * 64 + s * 8 + 2 * w;
            const int x1 = tX * 64 + 2 * l;
            float2* o0 = reinterpret_cast<float2*>(out + OFF1 +
                           ((size_t)(f * 1024 + y1) * 1024 + x1) * 3);
            float2* o1 = reinterpret_cast<float2*>(out + OFF1 +
                           ((size_t)(f * 1024 + y1 + 1) * 1024 + x1) * 3);
            o0[0] = make_float2(p00r, p00g);
            o0[1] = make_float2(p00b, p01r);
            o0[2] = make_float2(p01g, p01b);
            o1[0] = make_float2(p10r, p10g);
            o1[1] = make_float2(p10b, p11r);
            o1[2] = make_float2(p11g, p11b);

            // mip2 px (row s*4+w, col l) entirely in registers
            const float vr = (p00r + p01r + p10r + p11r) * 0.25f;
            const float vg = (p00g + p01g + p10g + p11g) * 0.25f;
            const float vb = (p00b + p01b + p10b + p11b) * 0.25f;
            const int y2 = tY * 32 + s * 4 + w;
            const int x2 = tX * 32 + l;
            float* og = out + OFF2 + ((size_t)(f * 512 + y2) * 512 + x2) * 3;
            og[0] = vr; og[1] = vg; og[2] = vb;
            float* m2 = sm + S_M2 + (s * 4 + w) * 96 + l * 3;
            m2[0] = vr; m2[1] = vg; m2[2] = vb;
        }
        // no second barrier: buf[(s+1)&1] was last read in iter s-1, fenced by
        // the single barrier of iter s; m2 regions are per-(s,w) disjoint.
    }
    __syncthreads();

    // ---- mip3: 16x16, 1 px per thread ----
    {
        const int r = t >> 4, c = t & 15;
        const float* pa = sm + S_M2 + (2 * r) * 96 + c * 6;
        const float* pb = pa + 96;
        const float vr = (pa[0] + pa[3] + pb[0] + pb[3]) * 0.25f;
        const float vg = (pa[1] + pa[4] + pb[1] + pb[4]) * 0.25f;
        const float vb = (pa[2] + pa[5] + pb[2] + pb[5]) * 0.25f;
        float* o = out + OFF3 + ((size_t)(f * 256 + tY * 16 + r) * 256 + tX * 16 + c) * 3;
        o[0] = vr; o[1] = vg; o[2] = vb;
        float* m3 = sm + S_M3 + r * 48 + c * 3;
        m3[0] = vr; m3[1] = vg; m3[2] = vb;
    }
    __syncthreads();

    // ---- mip4: 8x8 ----
    if (t < 64) {
        const int r = t >> 3, c = t & 7;
        const float* pa = sm + S_M3 + (2 * r) * 48 + c * 6;
        const float* pb = pa + 48;
        const float vr = (pa[0] + pa[3] + pb[0] + pb[3]) * 0.25f;
        const float vg = (pa[1] + pa[4] + pb[1] + pb[4]) * 0.25f;
        const float vb = (pa[2] + pa[5] + pb[2] + pb[5]) * 0.25f;
        float* o = out + OFF4 + ((size_t)(f * 128 + tY * 8 + r) * 128 + tX * 8 + c) * 3;
        o[0] = vr; o[1] = vg; o[2] = vb;
        float* m4 = sm + S_M4 + r * 24 + c * 3;
        m4[0] = vr; m4[1] = vg; m4[2] = vb;
    }
    __syncthreads();

    // ---- mip5: 4x4 ----
    if (t < 16) {
        const int r = t >> 2, c = t & 3;
        const float* pa = sm + S_M4 + (2 * r) * 24 + c * 6;
        const float* pb = pa + 24;
        const float vr = (pa[0] + pa[3] + pb[0] + pb[3]) * 0.25f;
        const float vg = (pa[1] + pa[4] + pb[1] + pb[4]) * 0.25f;
        const float vb = (pa[2] + pa[5] + pb[2] + pb[5]) * 0.25f;
        float* o = out + OFF5 + ((size_t)(f * 64 + tY * 4 + r) * 64 + tX * 4 + c) * 3;
        o[0] = vr; o[1] = vg; o[2] = vb;
        float* m5 = sm + S_M5 + r * 12 + c * 3;
        m5[0] = vr; m5[1] = vg; m5[2] = vb;
    }
    __syncthreads();

    // ---- mip6: 2x2 ----
    if (t < 4) {
        const int r = t >> 1, c = t & 1;
        const float* pa = sm + S_M5 + (2 * r) * 12 + c * 6;
        const float* pb = pa + 12;
        const float vr = (pa[0] + pa[3] + pb[0] + pb[3]) * 0.25f;
        const float vg = (pa[1] + pa[4] + pb[1] + pb[4]) * 0.25f;
        const float vb = (pa[2] + pa[5] + pb[2] + pb[5]) * 0.25f;
        float* o = out + OFF6 + ((size_t)(f * 32 + tY * 2 + r) * 32 + tX * 2 + c) * 3;
        o[0] = vr; o[1] = vg; o[2] = vb;
        float* m6 = sm + S_M6 + r * 6 + c * 3;
        m6[0] = vr; m6[1] = vg; m6[2] = vb;
    }
    __syncthreads();

    // ---- mip7: 1 px per block ----
    if (t == 0) {
        const float* m6 = sm + S_M6;
        float* o = out + OFF7 + ((size_t)(f * 16 + tY) * 16 + tX) * 3;
        #pragma unroll
        for (int c = 0; c < 3; c++)
            o[c] = (m6[c] + m6[3 + c] + m6[6 + c] + m6[9 + c]) * 0.25f;
    }
}

extern "C" void kernel_launch(void* const* d_in, const int* in_sizes, int n_in,
                              void* d_out, int out_size) {
    const float* base = (const float*)d_in[0];
    float* out = (float*)d_out;
    dim3 g(16, 16, 6);
    mip_all<<<g, 256>>>(base, out);
}

// round 11
// speedup vs baseline: 1.0707x; 1.0367x over previous
#include <cuda_runtime.h>
#include <cstddef>

// Mip chain: [6, 2048, 2048, 3] f32 -> repeated 2x2 avg pool down to 16.
// Output = concat(base, mip1..mip7).

#define R0 2048
#define OFF1 75497472ull
#define OFF2 94371840ull
#define OFF3 99090432ull
#define OFF4 100270080ull
#define OFF5 100564992ull
#define OFF6 100638720ull
#define OFF7 100657152ull

// ---------------- Kernel A: 64x64 tiles -> L0 copy + mip1 + mip2 + mip3 ----
// smem (floats): slab sums 16x192=3072 | m1 16x96=1536 | m2 16x48=768
#define S_SLAB 0
#define S_M1   3072
#define S_M2   4608
#define A_SMEM 5376

__global__ __launch_bounds__(256) void mip_stageA(const float* __restrict__ base,
                                                  float* __restrict__ out) {
    __shared__ float sm[A_SMEM];
    const int f  = blockIdx.z;
    const int tX = blockIdx.x;   // 0..31
    const int tY = blockIdx.y;   // 0..31
    const int t  = threadIdx.x;  // 0..255

    // 768 units per 32-row slab: unit = (row-pair 0..15) * 48 + f4col
    int aa[3], cc[3];
    #pragma unroll
    for (int k = 0; k < 3; k++) {
        const int unit = k * 256 + t;
        aa[k] = unit / 48;
        cc[k] = unit - aa[k] * 48;
    }

    const size_t tile = ((size_t)(f * R0 + tY * 64) * R0 + tX * 64) * 3;

    // preload slab 0 (raw rows held in regs until L0 store)
    float4 va[3], vb[3];
    #pragma unroll
    for (int k = 0; k < 3; k++) {
        const size_t g0 = tile + (size_t)(2 * aa[k]) * (R0 * 3);
        va[k] = reinterpret_cast<const float4*>(base + g0)[cc[k]];
        vb[k] = reinterpret_cast<const float4*>(base + g0 + (size_t)(R0 * 3))[cc[k]];
    }

    #pragma unroll
    for (int s = 0; s < 2; s++) {
        // ---- L0 copy + publish vertical sums ----
        #pragma unroll
        for (int k = 0; k < 3; k++) {
            const size_t g0 = tile + (size_t)(s * 32 + 2 * aa[k]) * (R0 * 3);
            reinterpret_cast<float4*>(out + g0)[cc[k]] = va[k];
            reinterpret_cast<float4*>(out + g0 + (size_t)(R0 * 3))[cc[k]] = vb[k];
            float4 sv;
            sv.x = va[k].x + vb[k].x; sv.y = va[k].y + vb[k].y;
            sv.z = va[k].z + vb[k].z; sv.w = va[k].w + vb[k].w;
            reinterpret_cast<float4*>(sm + S_SLAB)[aa[k] * 48 + cc[k]] = sv;
        }
        __syncthreads();

        // ---- prefetch slab 1 while mip1/mip2 run ----
        if (s == 0) {
            #pragma unroll
            for (int k = 0; k < 3; k++) {
                const size_t g0 = tile + (size_t)(32 + 2 * aa[k]) * (R0 * 3);
                va[k] = reinterpret_cast<const float4*>(base + g0)[cc[k]];
                vb[k] = reinterpret_cast<const float4*>(base + g0 + (size_t)(R0 * 3))[cc[k]];
            }
        }

        // ---- mip1: 16 rows x 32 px, 2 px per thread ----
        {
            const int r1 = t >> 4;            // 0..15
            const int c1 = (t & 15) * 2;      // even
            const float* in = sm + S_SLAB + r1 * 192 + c1 * 6;  // vertical sums
            const float v0 = (in[0] + in[3]) * 0.25f;
            const float v1 = (in[1] + in[4]) * 0.25f;
            const float v2 = (in[2] + in[5]) * 0.25f;
            const float v3 = (in[6] + in[9]) * 0.25f;
            const float v4 = (in[7] + in[10]) * 0.25f;
            const float v5 = (in[8] + in[11]) * 0.25f;
            const int y1 = tY * 32 + s * 16 + r1;
            const int x1 = tX * 32 + c1;
            float2* o = reinterpret_cast<float2*>(out + OFF1 +
                          ((size_t)(f * 1024 + y1) * 1024 + x1) * 3);
            o[0] = make_float2(v0, v1);
            o[1] = make_float2(v2, v3);
            o[2] = make_float2(v4, v5);
            float* m1 = sm + S_M1 + r1 * 96 + c1 * 3;
            m1[0] = v0; m1[1] = v1; m1[2] = v2;
            m1[3] = v3; m1[4] = v4; m1[5] = v5;
        }
        __syncthreads();

        // ---- mip2: 8 rows x 16 px (threads 0..127) ----
        if (t < 128) {
            const int r2 = t >> 4;            // 0..7
            const int c2 = t & 15;
            const float* ra = sm + S_M1 + (2 * r2) * 96 + c2 * 6;
            const float* rb = ra + 96;
            const float vr = (ra[0] + ra[3] + rb[0] + rb[3]) * 0.25f;
            const float vg = (ra[1] + ra[4] + rb[1] + rb[4]) * 0.25f;
            const float vb2 = (ra[2] + ra[5] + rb[2] + rb[5]) * 0.25f;
            const int y2 = tY * 16 + s * 8 + r2;
            const int x2 = tX * 16 + c2;
            float* o = out + OFF2 + ((size_t)(f * 512 + y2) * 512 + x2) * 3;
            o[0] = vr; o[1] = vg; o[2] = vb2;
            float* m2 = sm + S_M2 + (s * 8 + r2) * 48 + c2 * 3;
            m2[0] = vr; m2[1] = vg; m2[2] = vb2;
        }
        __syncthreads();    // slab buf + m1 free for next iteration
    }

    // ---- mip3: 8x8 (threads 0..63), global only ----
    if (t < 64) {
        const int r = t >> 3, c = t & 7;
        const float* ra = sm + S_M2 + (2 * r) * 48 + c * 6;
        const float* rb = ra + 48;
        const float vr = (ra[0] + ra[3] + rb[0] + rb[3]) * 0.25f;
        const float vg = (ra[1] + ra[4] + rb[1] + rb[4]) * 0.25f;
        const float vb2 = (ra[2] + ra[5] + rb[2] + rb[5]) * 0.25f;
        float* o = out + OFF3 + ((size_t)(f * 256 + tY * 8 + r) * 256 + tX * 8 + c) * 3;
        o[0] = vr; o[1] = vg; o[2] = vb2;
    }
}

// ---------------- Kernel B: mip3 -> mip4..mip7; 384 independent blocks -----
// block = 16x16 mip4 tile (64 blocks per face). mip3 is L2-resident (4.7MB).
#define B_M4 0          // 16x16x3 = 768
#define B_M5 768        // 8x8x3   = 192
#define B_M6 960        // 4x4x3   = 48
#define B_SMEM 1008

__global__ __launch_bounds__(256) void mip_stageB(float* __restrict__ out) {
    __shared__ float sm[B_SMEM];
    const int b   = blockIdx.x;        // 0..383
    const int f   = b >> 6;
    const int idx = b & 63;
    const int by  = idx >> 3, bx = idx & 7;
    const int t   = threadIdx.x;

    const float* m3 = out + OFF3 + (size_t)f * (256 * 256 * 3);
    float* m4 = out + OFF4 + (size_t)f * (128 * 128 * 3);
    float* m5 = out + OFF5 + (size_t)f * (64 * 64 * 3);
    float* m6 = out + OFF6 + (size_t)f * (32 * 32 * 3);
    float* m7 = out + OFF7 + (size_t)f * (16 * 16 * 3);

    // ---- mip4: 16x16 tile, 1 px per thread ----
    {
        const int r = t >> 4, c = t & 15;
        const int y4 = by * 16 + r, x4 = bx * 16 + c;
        const float2* pa = reinterpret_cast<const float2*>(m3 + ((2 * y4) * 256 + 2 * x4) * 3);
        const float2* pb = reinterpret_cast<const float2*>(m3 + ((2 * y4 + 1) * 256 + 2 * x4) * 3);
        const float2 a0 = pa[0], a1 = pa[1], a2 = pa[2];
        const float2 b0 = pb[0], b1 = pb[1], b2 = pb[2];
        const float vr = (a0.x + a1.y + b0.x + b1.y) * 0.25f;
        const float vg = (a0.y + a2.x + b0.y + b2.x) * 0.25f;
        const float vb = (a1.x + a2.y + b1.x + b2.y) * 0.25f;
        float* o = m4 + (y4 * 128 + x4) * 3;
        o[0] = vr; o[1] = vg; o[2] = vb;
        float* l = sm + B_M4 + (r * 16 + c) * 3;
        l[0] = vr; l[1] = vg; l[2] = vb;
    }
    __syncthreads();

    // ---- mip5: 8x8 (threads 0..63) ----
    if (t < 64) {
        const int r = t >> 3, c = t & 7;
        const float* pa = sm + B_M4 + ((2 * r) * 16 + 2 * c) * 3;
        const float* pb = pa + 16 * 3;
        const float vr = (pa[0] + pa[3] + pb[0] + pb[3]) * 0.25f;
        const float vg = (pa[1] + pa[4] + pb[1] + pb[4]) * 0.25f;
        const float vb = (pa[2] + pa[5] + pb[2] + pb[5]) * 0.25f;
        float* o = m5 + ((by * 8 + r) * 64 + bx * 8 + c) * 3;
        o[0] = vr; o[1] = vg; o[2] = vb;
        float* l = sm + B_M5 + (r * 8 + c) * 3;
        l[0] = vr; l[1] = vg; l[2] = vb;
    }
    __syncthreads();

    // ---- mip6: 4x4 (threads 0..15) ----
    if (t < 16) {
        const int r = t >> 2, c = t & 3;
        const float* pa = sm + B_M5 + ((2 * r) * 8 + 2 * c) * 3;
        const float* pb = pa + 8 * 3;
        const float vr = (pa[0] + pa[3] + pb[0] + pb[3]) * 0.25f;
        const float vg = (pa[1] + pa[4] + pb[1] + pb[4]) * 0.25f;
        const float vb = (pa[2] + pa[5] + pb[2] + pb[5]) * 0.25f;
        float* o = m6 + ((by * 4 + r) * 32 + bx * 4 + c) * 3;
        o[0] = vr; o[1] = vg; o[2] = vb;
        float* l = sm + B_M6 + (r * 4 + c) * 3;
        l[0] = vr; l[1] = vg; l[2] = vb;
    }
    __syncthreads();

    // ---- mip7: 2x2 (threads 0..3) ----
    if (t < 4) {
        const int r = t >> 1, c = t & 1;
        const float* pa = sm + B_M6 + ((2 * r) * 4 + 2 * c) * 3;
        const float* pb = pa + 4 * 3;
        const float vr = (pa[0] + pa[3] + pb[0] + pb[3]) * 0.25f;
        const float vg = (pa[1] + pa[4] + pb[1] + pb[4]) * 0.25f;
        const float vb = (pa[2] + pa[5] + pb[2] + pb[5]) * 0.25f;
        float* o = m7 + ((by * 2 + r) * 16 + bx * 2 + c) * 3;
        o[0] = vr; o[1] = vg; o[2] = vb;
    }
}

extern "C" void kernel_launch(void* const* d_in, const int* in_sizes, int n_in,
                              void* d_out, int out_size) {
    const float* base = (const float*)d_in[0];
    float* out = (float*)d_out;
    dim3 gA(32, 32, 6);
    mip_stageA<<<gA, 256>>>(base, out);
    mip_stageB<<<384, 256>>>(out);
}

// round 12
// speedup vs baseline: 1.0710x; 1.0003x over previous
#include <cuda_runtime.h>
#include <cstddef>

// Mip chain: [6, 2048, 2048, 3] f32 -> repeated 2x2 avg pool down to 16.
// Output = concat(base, mip1..mip7).

#define R0 2048
#define OFF1 75497472ull
#define OFF2 94371840ull
#define OFF3 99090432ull
#define OFF4 100270080ull
#define OFF5 100564992ull
#define OFF6 100638720ull
#define OFF7 100657152ull

// ---------------- Kernel A: 64x64 tiles -> L0 copy + mip1..mip6 ------------
// smem (floats): slab sums 16x192=3072 | m1 16x96=1536 | m2 16x48=768 |
//                m3 8x24=192 | m4 4x12=48 | m5 2x6=12
#define S_SLAB 0
#define S_M1   3072
#define S_M2   4608
#define S_M3   5376
#define S_M4   5568
#define S_M5   5616
#define A_SMEM 5628

__global__ __launch_bounds__(256) void mip_stageA(const float* __restrict__ base,
                                                  float* __restrict__ out) {
    __shared__ float sm[A_SMEM];
    const int f  = blockIdx.z;
    const int tX = blockIdx.x;   // 0..31
    const int tY = blockIdx.y;   // 0..31
    const int t  = threadIdx.x;  // 0..255

    // 768 units per 32-row slab: unit = (row-pair 0..15) * 48 + f4col
    int aa[3], cc[3];
    #pragma unroll
    for (int k = 0; k < 3; k++) {
        const int unit = k * 256 + t;
        aa[k] = unit / 48;
        cc[k] = unit - aa[k] * 48;
    }

    const size_t tile = ((size_t)(f * R0 + tY * 64) * R0 + tX * 64) * 3;

    // preload slab 0 (raw rows held in regs until L0 store)
    float4 va[3], vb[3];
    #pragma unroll
    for (int k = 0; k < 3; k++) {
        const size_t g0 = tile + (size_t)(2 * aa[k]) * (R0 * 3);
        va[k] = reinterpret_cast<const float4*>(base + g0)[cc[k]];
        vb[k] = reinterpret_cast<const float4*>(base + g0 + (size_t)(R0 * 3))[cc[k]];
    }

    #pragma unroll
    for (int s = 0; s < 2; s++) {
        // ---- L0 copy + publish vertical sums ----
        #pragma unroll
        for (int k = 0; k < 3; k++) {
            const size_t g0 = tile + (size_t)(s * 32 + 2 * aa[k]) * (R0 * 3);
            reinterpret_cast<float4*>(out + g0)[cc[k]] = va[k];
            reinterpret_cast<float4*>(out + g0 + (size_t)(R0 * 3))[cc[k]] = vb[k];
            float4 sv;
            sv.x = va[k].x + vb[k].x; sv.y = va[k].y + vb[k].y;
            sv.z = va[k].z + vb[k].z; sv.w = va[k].w + vb[k].w;
            reinterpret_cast<float4*>(sm + S_SLAB)[aa[k] * 48 + cc[k]] = sv;
        }
        __syncthreads();

        // ---- prefetch slab 1 while mip1/mip2 run ----
        if (s == 0) {
            #pragma unroll
            for (int k = 0; k < 3; k++) {
                const size_t g0 = tile + (size_t)(32 + 2 * aa[k]) * (R0 * 3);
                va[k] = reinterpret_cast<const float4*>(base + g0)[cc[k]];
                vb[k] = reinterpret_cast<const float4*>(base + g0 + (size_t)(R0 * 3))[cc[k]];
            }
        }

        // ---- mip1: 16 rows x 32 px, 2 px per thread ----
        {
            const int r1 = t >> 4;            // 0..15
            const int c1 = (t & 15) * 2;      // even
            const float* in = sm + S_SLAB + r1 * 192 + c1 * 6;  // vertical sums
            const float v0 = (in[0] + in[3]) * 0.25f;
            const float v1 = (in[1] + in[4]) * 0.25f;
            const float v2 = (in[2] + in[5]) * 0.25f;
            const float v3 = (in[6] + in[9]) * 0.25f;
            const float v4 = (in[7] + in[10]) * 0.25f;
            const float v5 = (in[8] + in[11]) * 0.25f;
            const int y1 = tY * 32 + s * 16 + r1;
            const int x1 = tX * 32 + c1;
            float2* o = reinterpret_cast<float2*>(out + OFF1 +
                          ((size_t)(f * 1024 + y1) * 1024 + x1) * 3);
            o[0] = make_float2(v0, v1);
            o[1] = make_float2(v2, v3);
            o[2] = make_float2(v4, v5);
            float* m1 = sm + S_M1 + r1 * 96 + c1 * 3;
            m1[0] = v0; m1[1] = v1; m1[2] = v2;
            m1[3] = v3; m1[4] = v4; m1[5] = v5;
        }
        __syncthreads();

        // ---- mip2: 8 rows x 16 px (threads 0..127) ----
        if (t < 128) {
            const int r2 = t >> 4;            // 0..7
            const int c2 = t & 15;
            const float* ra = sm + S_M1 + (2 * r2) * 96 + c2 * 6;
            const float* rb = ra + 96;
            const float vr = (ra[0] + ra[3] + rb[0] + rb[3]) * 0.25f;
            const float vg = (ra[1] + ra[4] + rb[1] + rb[4]) * 0.25f;
            const float vb2 = (ra[2] + ra[5] + rb[2] + rb[5]) * 0.25f;
            const int y2 = tY * 16 + s * 8 + r2;
            const int x2 = tX * 16 + c2;
            float* o = out + OFF2 + ((size_t)(f * 512 + y2) * 512 + x2) * 3;
            o[0] = vr; o[1] = vg; o[2] = vb2;
            float* m2 = sm + S_M2 + (s * 8 + r2) * 48 + c2 * 3;
            m2[0] = vr; m2[1] = vg; m2[2] = vb2;
        }
        __syncthreads();    // slab buf + m1 free for next iteration
    }

    // ---- mip3: 8x8 (threads 0..63) ----
    if (t < 64) {
        const int r = t >> 3, c = t & 7;
        const float* ra = sm + S_M2 + (2 * r) * 48 + c * 6;
        const float* rb = ra + 48;
        const float vr = (ra[0] + ra[3] + rb[0] + rb[3]) * 0.25f;
        const float vg = (ra[1] + ra[4] + rb[1] + rb[4]) * 0.25f;
        const float vb2 = (ra[2] + ra[5] + rb[2] + rb[5]) * 0.25f;
        float* o = out + OFF3 + ((size_t)(f * 256 + tY * 8 + r) * 256 + tX * 8 + c) * 3;
        o[0] = vr; o[1] = vg; o[2] = vb2;
        float* m3 = sm + S_M3 + (r * 8 + c) * 3;
        m3[0] = vr; m3[1] = vg; m3[2] = vb2;
    }
    __syncthreads();

    // ---- mip4: 4x4 (threads 0..15) ----
    if (t < 16) {
        const int r = t >> 2, c = t & 3;
        const float* ra = sm + S_M3 + ((2 * r) * 8 + 2 * c) * 3;
        const float* rb = ra + 8 * 3;
        const float vr = (ra[0] + ra[3] + rb[0] + rb[3]) * 0.25f;
        const float vg = (ra[1] + ra[4] + rb[1] + rb[4]) * 0.25f;
        const float vb2 = (ra[2] + ra[5] + rb[2] + rb[5]) * 0.25f;
        float* o = out + OFF4 + ((size_t)(f * 128 + tY * 4 + r) * 128 + tX * 4 + c) * 3;
        o[0] = vr; o[1] = vg; o[2] = vb2;
        float* m4 = sm + S_M4 + (r * 4 + c) * 3;
        m4[0] = vr; m4[1] = vg; m4[2] = vb2;
    }
    __syncthreads();

    // ---- mip5: 2x2 (threads 0..3) ----
    if (t < 4) {
        const int r = t >> 1, c = t & 1;
        const float* ra = sm + S_M4 + ((2 * r) * 4 + 2 * c) * 3;
        const float* rb = ra + 4 * 3;
        const float vr = (ra[0] + ra[3] + rb[0] + rb[3]) * 0.25f;
        const float vg = (ra[1] + ra[4] + rb[1] + rb[4]) * 0.25f;
        const float vb2 = (ra[2] + ra[5] + rb[2] + rb[5]) * 0.25f;
        float* o = out + OFF5 + ((size_t)(f * 64 + tY * 2 + r) * 64 + tX * 2 + c) * 3;
        o[0] = vr; o[1] = vg; o[2] = vb2;
        float* m5 = sm + S_M5 + (r * 2 + c) * 3;
        m5[0] = vr; m5[1] = vg; m5[2] = vb2;
    }
    __syncthreads();

    // ---- mip6: 1 px per block ----
    if (t == 0) {
        const float* m5 = sm + S_M5;
        float* o = out + OFF6 + ((size_t)(f * 32 + tY) * 32 + tX) * 3;
        #pragma unroll
        for (int c = 0; c < 3; c++)
            o[c] = (m5[c] + m5[3 + c] + m5[6 + c] + m5[9 + c]) * 0.25f;
    }
}

// ---------------- Kernel B: mip6 (32x32/face) -> mip7 (16x16/face) ---------
// 6 blocks; 256 threads = one mip7 px each. mip6 is L2-hot (73KB total).
__global__ __launch_bounds__(256) void mip_stageB(float* __restrict__ out) {
    const int f = blockIdx.x;
    const int t = threadIdx.x;
    const int r = t >> 4, c = t & 15;

    const float* m6 = out + OFF6 + (size_t)f * (32 * 32 * 3);
    float* m7 = out + OFF7 + (size_t)f * (16 * 16 * 3);

    const float* pa = m6 + ((2 * r) * 32 + 2 * c) * 3;
    const float* pb = pa + 32 * 3;
    const float vr = (pa[0] + pa[3] + pb[0] + pb[3]) * 0.25f;
    const float vg = (pa[1] + pa[4] + pb[1] + pb[4]) * 0.25f;
    const float vb = (pa[2] + pa[5] + pb[2] + pb[5]) * 0.25f;
    float* o = m7 + (r * 16 + c) * 3;
    o[0] = vr; o[1] = vg; o[2] = vb;
}

extern "C" void kernel_launch(void* const* d_in, const int* in_sizes, int n_in,
                              void* d_out, int out_size) {
    const float* base = (const float*)d_in[0];
    float* out = (float*)d_out;
    dim3 gA(32, 32, 6);
    mip_stageA<<<gA, 256>>>(base, out);
    mip_stageB<<<6, 256>>>(out);
}